// round 14
// baseline (speedup 1.0000x reference)
#include <cuda_runtime.h>
#include <cuda_bf16.h>
#include <cuda_fp16.h>
#include <cstdint>

// ---------------- problem constants ----------------
constexpr int N_TOK  = 2048 * 64;   // 131072 tokens
constexpr int EMB    = 384;
constexpr int NHEAD  = 8;
constexpr int HSZ    = 48;
constexpr int SEQ    = 64;
constexpr int FF     = 1536;
constexpr float ATT_SCALE = 2.449489742783178f;

// ---------------- scratch (static device memory) ----------------
__device__ __align__(128) __nv_bfloat16 g_ln1 [(size_t)N_TOK * 2 * EMB];    // [hi|lo] for QK
__device__ __align__(128) __half        g_h1h [(size_t)N_TOK * EMB];        // fp16 LN1 (for V)
__device__ __align__(128) float         g_qk  [(size_t)N_TOK * 2 * EMB];    // fp32 q|k
__device__ __align__(128) __half        g_vh  [(size_t)N_TOK * EMB];        // fp16 v
__device__ __align__(128) __half        g_attnh[(size_t)N_TOK * EMB];       // fp16
__device__ __align__(128) float         g_x2  [(size_t)N_TOK * EMB];        // fp32 residual
__device__ __align__(128) __half        g_h2h [(size_t)N_TOK * EMB];        // fp16
__device__ __align__(128) __half        g_hidh[(size_t)N_TOK * FF];         // fp16
__device__ __align__(128) __nv_bfloat16 g_wqk [(size_t)(2*EMB) * 2 * EMB];  // [768][hi|lo 768]
__device__ __align__(128) __half        g_wvh [(size_t)EMB * EMB];          // [N][K] fp16
__device__ __align__(128) __half        g_wph [(size_t)EMB * EMB];
__device__ __align__(128) __half        g_w1h [(size_t)FF  * EMB];
__device__ __align__(128) __half        g_w2h [(size_t)EMB * FF];
__device__ int g_sem[N_TOK / 128];   // proj->LN2 fusion semaphores

// ---------------- PTX helpers ----------------
typedef unsigned long long u64;
__device__ __forceinline__ uint32_t smem_u32(const void* p) {
    uint32_t a;
    asm("{ .reg .u64 t; cvta.to.shared.u64 t, %1; cvt.u32.u64 %0, t; }" : "=r"(a) : "l"(p));
    return a;
}
#define CPASYNC16(dst, src) asm volatile("cp.async.cg.shared.global [%0], [%1], 16;" :: "r"(dst), "l"(src) : "memory")
#define CP_COMMIT()         asm volatile("cp.async.commit_group;" ::: "memory")
#define CP_WAIT1()          asm volatile("cp.async.wait_group 1;" ::: "memory")
#define CP_WAIT0()          asm volatile("cp.async.wait_group 0;" ::: "memory")

#define LDSM4(r, addr) \
    asm volatile("ldmatrix.sync.aligned.m8n8.x4.shared.b16 {%0,%1,%2,%3}, [%4];" \
        : "=r"((r)[0]), "=r"((r)[1]), "=r"((r)[2]), "=r"((r)[3]) : "r"(addr))

#define MMA_BF16(d, a, b0, b1) \
    asm volatile("mma.sync.aligned.m16n8k16.row.col.f32.bf16.bf16.f32 " \
        "{%0,%1,%2,%3}, {%4,%5,%6,%7}, {%8,%9}, {%0,%1,%2,%3};" \
        : "+f"((d)[0]), "+f"((d)[1]), "+f"((d)[2]), "+f"((d)[3]) \
        : "r"((a)[0]), "r"((a)[1]), "r"((a)[2]), "r"((a)[3]), "r"(b0), "r"(b1))

#define MMA_FP16(d, a, b0, b1) \
    asm volatile("mma.sync.aligned.m16n8k16.row.col.f32.f16.f16.f32 " \
        "{%0,%1,%2,%3}, {%4,%5,%6,%7}, {%8,%9}, {%0,%1,%2,%3};" \
        : "+f"((d)[0]), "+f"((d)[1]), "+f"((d)[2]), "+f"((d)[3]) \
        : "r"((a)[0]), "r"((a)[1]), "r"((a)[2]), "r"((a)[3]), "r"(b0), "r"(b1))

__device__ __forceinline__ u64 pk2(float lo, float hi) {
    u64 r; asm("mov.b64 %0, {%1, %2};" : "=l"(r) : "f"(lo), "f"(hi)); return r;
}
__device__ __forceinline__ float2 upk2(u64 p) {
    float2 r; asm("mov.b64 {%0, %1}, %2;" : "=f"(r.x), "=f"(r.y) : "l"(p)); return r;
}
#define FMA2(d, a, b) asm("fma.rn.f32x2 %0, %1, %2, %0;" : "+l"(d) : "l"(a), "l"(b))
#define MUL2(d, a, b) asm("mul.rn.f32x2 %0, %1, %2;" : "=l"(d) : "l"(a), "l"(b))

__device__ __forceinline__ __nv_bfloat16 bf_hi(float v) { return __float2bfloat16(v); }
__device__ __forceinline__ __nv_bfloat16 bf_lo(float v, __nv_bfloat16 hi) {
    return __float2bfloat16(v - __bfloat162float(hi));
}

// ---------------- stage 1: LN1 fused with ALL weight prep (+sem zero) ----------------
constexpr int LN_BLOCKS   = N_TOK / 4;
constexpr int PREP_TOTAL  = 147456 + 147456 + 589824 + 589824;
constexpr int PREP_BLOCKS = PREP_TOTAL / 512;

__global__ void __launch_bounds__(128)
stage1_kernel(const float* __restrict__ in, const float* __restrict__ g,
              const float* __restrict__ b, __nv_bfloat16* __restrict__ bfout,
              __half* __restrict__ hout,
              const float* __restrict__ Wq, const float* __restrict__ Wk,
              const float* __restrict__ Wv, const float* __restrict__ Wp,
              const float* __restrict__ W1, const float* __restrict__ W2) {
    if (blockIdx.x < 8) {
        int i = blockIdx.x * 128 + threadIdx.x;
        if (i < N_TOK / 128) g_sem[i] = 0;
    }
    if (blockIdx.x < LN_BLOCKS) {
        const int row = blockIdx.x * 4 + (threadIdx.x >> 5);
        const int lane = threadIdx.x & 31;
        const float* rp = in + (size_t)row * EMB + lane * 12;
        float4 v0 = *(const float4*)(rp), v1 = *(const float4*)(rp + 4), v2 = *(const float4*)(rp + 8);
        float vv[12] = {v0.x, v0.y, v0.z, v0.w, v1.x, v1.y, v1.z, v1.w, v2.x, v2.y, v2.z, v2.w};
        float s = 0.0f, ss = 0.0f;
        #pragma unroll
        for (int i = 0; i < 12; i++) { s += vv[i]; ss += vv[i] * vv[i]; }
        #pragma unroll
        for (int off = 16; off > 0; off >>= 1) {
            s  += __shfl_xor_sync(0xffffffffu, s, off);
            ss += __shfl_xor_sync(0xffffffffu, ss, off);
        }
        float mu = s * (1.0f / EMB);
        float var = ss * (1.0f / EMB) - mu * mu;
        float rs = rsqrtf(var + 1e-5f);
        const float* gp = g + lane * 12;
        const float* bp = b + lane * 12;
        float o[12];
        #pragma unroll
        for (int i = 0; i < 12; i++) o[i] = (vv[i] - mu) * rs * gp[i] + bp[i];
        __half hh[12];
        #pragma unroll
        for (int i = 0; i < 12; i++) hh[i] = __float2half(o[i]);
        __half* hrow = hout + (size_t)row * EMB + lane * 12;
        *(uint2*)(hrow)     = *(uint2*)(hh);
        *(uint2*)(hrow + 4) = *(uint2*)(hh + 4);
        *(uint2*)(hrow + 8) = *(uint2*)(hh + 8);
        __nv_bfloat16 hi[12], lo[12];
        #pragma unroll
        for (int i = 0; i < 12; i++) { hi[i] = bf_hi(o[i]); lo[i] = bf_lo(o[i], hi[i]); }
        __nv_bfloat16* orow = bfout + (size_t)row * 2 * EMB + lane * 12;
        *(uint2*)(orow)     = *(uint2*)(hi);
        *(uint2*)(orow + 4) = *(uint2*)(hi + 4);
        *(uint2*)(orow + 8) = *(uint2*)(hi + 8);
        __nv_bfloat16* lrow = orow + EMB;
        *(uint2*)(lrow)     = *(uint2*)(lo);
        *(uint2*)(lrow + 4) = *(uint2*)(lo + 4);
        *(uint2*)(lrow + 8) = *(uint2*)(lo + 8);
    } else {
        int base = (blockIdx.x - LN_BLOCKS) * 512 + threadIdx.x * 4;
        #pragma unroll
        for (int e = 0; e < 4; e++) {
            int i = base + e;
            if (i < 147456) {
                int h = i / (EMB * HSZ), r = i % (EMB * HSZ), c = r / HSZ, d = r % HSZ;
                int n = h * HSZ + d;
                float q = Wq[i], k = Wk[i];
                __nv_bfloat16 qh = bf_hi(q), kh = bf_hi(k);
                size_t rq = (size_t)n * 2 * EMB, rk = (size_t)(EMB + n) * 2 * EMB;
                g_wqk[rq + c] = qh;  g_wqk[rq + EMB + c] = bf_lo(q, qh);
                g_wqk[rk + c] = kh;  g_wqk[rk + EMB + c] = bf_lo(k, kh);
                g_wvh[(size_t)n * EMB + c] = __float2half(Wv[i]);
            } else if (i < 294912) {
                int j = i - 147456;
                int k = j / EMB, n = j % EMB;
                g_wph[(size_t)n * EMB + k] = __float2half(Wp[j]);
            } else if (i < 884736) {
                int j = i - 294912;
                int k = j / FF, n = j % FF;
                g_w1h[(size_t)n * EMB + k] = __float2half(W1[j]);
            } else {
                int j = i - 884736;
                int k = j / EMB, n = j % EMB;
                g_w2h[(size_t)n * FF + k] = __float2half(W2[j]);
            }
        }
    }
}

// ---------------- tiling constants ----------------
constexpr int PC128  = 128 * 144;     // 18432 (128-row piece)
constexpr int PC64   = 64 * 144;      // 9216  (64-row piece)
constexpr int FSTG2  = 2 * PC128;                 // 36864 (fp16 stage)
constexpr int GSMEM2 = 3 * FSTG2;                 // 110592 -> 2 CTAs/SM
constexpr int QSTG   = 2 * PC128 + 2 * PC64;      // 55296 (QK stage: Ah|Al|Bh|Bl)
constexpr int VSTG   = PC128 + PC64;              // 27648 (V stage)
constexpr int GSMEMQ = 2 * QSTG;                  // 110592 -> 2 CTAs/SM

// ================= fp16 GEMM: 256 thr, BM=128/BN=128, warp tile 64x32, 2 CTA/SM =================
// MODE 1: fp32=acc+bias+res   2: fp16=relu(acc+bias)   3: MODE1 + fused LN2 (proj)
template<int MODE, int KST>
__global__ void __launch_bounds__(256, 2)
gemm16(const __half* __restrict__ A, const __half* __restrict__ B,
       const float* __restrict__ bias, const float* __restrict__ res,
       void* __restrict__ out, int Ntot,
       const float* __restrict__ g2, const float* __restrict__ b2v,
       __half* __restrict__ h2out) {
    extern __shared__ char smem[];
    const uint32_t sbase = smem_u32(smem);
    const int tid = threadIdx.x, lane = tid & 31, wid = tid >> 5;
    const int wm = wid >> 2, wn = wid & 3;
    const int m0 = blockIdx.y * 128, n0 = blockIdx.x * 128;
    constexpr int Kw = KST * 64;

    const int lrow = tid >> 1, lh = tid & 1;
    const __half* agp = A + (size_t)(m0 + lrow) * Kw + lh * 32;
    const __half* bgp = B + (size_t)(n0 + lrow) * Kw + lh * 32;
    const uint32_t ldst = (uint32_t)(lrow * 144 + lh * 64);

#define LOAD_F(bufi, k0v) do { \
        const uint32_t sb = sbase + (bufi) * FSTG2; \
        const __half* _a = agp + (k0v); \
        CPASYNC16(sb + ldst,      _a);      CPASYNC16(sb + ldst + 16, _a + 8); \
        CPASYNC16(sb + ldst + 32, _a + 16); CPASYNC16(sb + ldst + 48, _a + 24); \
        const __half* _b = bgp + (k0v); \
        CPASYNC16(sb + PC128 + ldst,      _b);      CPASYNC16(sb + PC128 + ldst + 16, _b + 8); \
        CPASYNC16(sb + PC128 + ldst + 32, _b + 16); CPASYNC16(sb + PC128 + ldst + 48, _b + 24); \
    } while (0)

    float d[4][4][4];
    #pragma unroll
    for (int i = 0; i < 4; i++)
        #pragma unroll
        for (int j = 0; j < 4; j++)
            #pragma unroll
            for (int q = 0; q < 4; q++) d[i][j][q] = 0.0f;

    const uint32_t a_off = (uint32_t)((wm * 64 + (lane & 15)) * 144 + (lane >> 4) * 16);
    const int nl = (lane & 7) + ((lane >> 4) << 3);
    const int kc = (lane >> 3) & 1;
    const uint32_t b_off = (uint32_t)((wn * 32 + nl) * 144 + kc * 16);

    LOAD_F(0, 0);  CP_COMMIT();
    LOAD_F(1, 64); CP_COMMIT();

    for (int it = 0; it < KST; it++) {
        CP_WAIT1();
        __syncthreads();
        if (it + 2 < KST) LOAD_F((it + 2) % 3, (it + 2) * 64);
        CP_COMMIT();

        const uint32_t sA = sbase + (it % 3) * FSTG2;
        const uint32_t sB = sA + PC128;
        #pragma unroll
        for (int kk = 0; kk < 4; kk++) {
            uint32_t a[4][4], b[2][4];
            #pragma unroll
            for (int mi = 0; mi < 4; mi++)
                LDSM4(a[mi], sA + a_off + mi * (16 * 144) + kk * 32);
            #pragma unroll
            for (int np = 0; np < 2; np++)
                LDSM4(b[np], sB + b_off + np * (16 * 144) + kk * 32);
            #pragma unroll
            for (int mi = 0; mi < 4; mi++)
                #pragma unroll
                for (int np = 0; np < 2; np++)
                    #pragma unroll
                    for (int sub = 0; sub < 2; sub++)
                        MMA_FP16(d[mi][np * 2 + sub], a[mi], b[np][sub*2], b[np][sub*2+1]);
        }
    }
#undef LOAD_F

    #pragma unroll
    for (int mi = 0; mi < 4; mi++) {
        int row0 = m0 + wm * 64 + mi * 16 + (lane >> 2);
        #pragma unroll
        for (int ni = 0; ni < 4; ni++) {
            int col = n0 + wn * 32 + ni * 8 + (lane & 3) * 2;
            if (MODE == 1 || MODE == 3) {
                float b0 = bias[col], b1 = bias[col + 1];
                float* o = (float*)out;
                float2 r0 = *(const float2*)(res + (size_t)row0 * Ntot + col);
                float2 r1 = *(const float2*)(res + (size_t)(row0 + 8) * Ntot + col);
                *(float2*)(o + (size_t)row0 * Ntot + col) =
                    make_float2(d[mi][ni][0] + b0 + r0.x, d[mi][ni][1] + b1 + r0.y);
                *(float2*)(o + (size_t)(row0 + 8) * Ntot + col) =
                    make_float2(d[mi][ni][2] + b0 + r1.x, d[mi][ni][3] + b1 + r1.y);
            } else {
                float b0 = bias[col], b1 = bias[col + 1];
                __half* ob = (__half*)out;
                *(__half2*)(ob + (size_t)row0 * Ntot + col) =
                    __floats2half2_rn(fmaxf(d[mi][ni][0] + b0, 0.0f), fmaxf(d[mi][ni][1] + b1, 0.0f));
                *(__half2*)(ob + (size_t)(row0 + 8) * Ntot + col) =
                    __floats2half2_rn(fmaxf(d[mi][ni][2] + b0, 0.0f), fmaxf(d[mi][ni][3] + b1, 0.0f));
            }
        }
    }

    if (MODE == 3) {
        __threadfence();
        __syncthreads();
        __shared__ int elect;
        if (tid == 0) {
            int old = atomicAdd(&g_sem[blockIdx.y], 1);
            elect = (old == 2);
        }
        __syncthreads();
        if (elect) {
            __threadfence();
            const float* x2f = (const float*)out;
            const int lane_ = tid & 31, wrp = tid >> 5;
            for (int rr = wrp; rr < 128; rr += 8) {
                int row = m0 + rr;
                const float* rp = x2f + (size_t)row * EMB + lane_ * 12;
                float4 v0 = *(const float4*)(rp), v1 = *(const float4*)(rp + 4), v2 = *(const float4*)(rp + 8);
                float vv[12] = {v0.x, v0.y, v0.z, v0.w, v1.x, v1.y, v1.z, v1.w, v2.x, v2.y, v2.z, v2.w};
                float s = 0.0f, ss = 0.0f;
                #pragma unroll
                for (int i = 0; i < 12; i++) { s += vv[i]; ss += vv[i] * vv[i]; }
                #pragma unroll
                for (int off = 16; off > 0; off >>= 1) {
                    s  += __shfl_xor_sync(0xffffffffu, s, off);
                    ss += __shfl_xor_sync(0xffffffffu, ss, off);
                }
                float mu = s * (1.0f / EMB);
                float var = ss * (1.0f / EMB) - mu * mu;
                float rs = rsqrtf(var + 1e-5f);
                const float* gp = g2 + lane_ * 12;
                const float* bp = b2v + lane_ * 12;
                __half hh[12];
                #pragma unroll
                for (int i = 0; i < 12; i++) hh[i] = __float2half((vv[i] - mu) * rs * gp[i] + bp[i]);
                __half* hrow = h2out + (size_t)row * EMB + lane_ * 12;
                *(uint2*)(hrow)     = *(uint2*)(hh);
                *(uint2*)(hrow + 4) = *(uint2*)(hh + 4);
                *(uint2*)(hrow + 8) = *(uint2*)(hh + 8);
            }
        }
    }
}

// ================= fat QKV kernel: 256 thr, BM=128, BN=64, 2 CTAs/SM =================
// blockIdx.x < 12: QK 3-pass bf16 (2-stage ring); >= 12: V 1-pass fp16 (3-stage ring).
__global__ void __launch_bounds__(256, 2)
gemm_qkv(const __nv_bfloat16* __restrict__ Aqk, const __nv_bfloat16* __restrict__ Bqk,
         const __half* __restrict__ Av, const __half* __restrict__ Bv,
         float* __restrict__ out_qk, __half* __restrict__ out_v) {
    extern __shared__ char smem[];
    const uint32_t sbase = smem_u32(smem);
    const int tid = threadIdx.x, lane = tid & 31, wid = tid >> 5;
    const int wm = wid >> 2, wn = wid & 3;   // 2 x 4 warp grid: warp tile 64x16
    const int m0 = blockIdx.y * 128;
    // A loader: 2 thr/row (64B each); B loader: 4 thr/row (32B each) over 64 rows
    const int arow = tid >> 1, ah = tid & 1;
    const int brow = tid >> 2, bq = tid & 3;
    const uint32_t adst = (uint32_t)(arow * 144 + ah * 64);
    const uint32_t bdst = (uint32_t)(brow * 144 + bq * 32);
    const uint32_t a_off = (uint32_t)((wm * 64 + (lane & 15)) * 144 + (lane >> 4) * 16);
    const int nl = (lane & 7) + ((lane >> 4) << 3);
    const int kc = (lane >> 3) & 1;
    const uint32_t b_off = (uint32_t)((wn * 16 + nl) * 144 + kc * 16);

    float d[4][2][4];
    #pragma unroll
    for (int i = 0; i < 4; i++)
        #pragma unroll
        for (int j = 0; j < 2; j++)
            #pragma unroll
            for (int q = 0; q < 4; q++) d[i][j][q] = 0.0f;

    if (blockIdx.x < 12) {
        const int n0 = blockIdx.x * 64;
        const __nv_bfloat16* agp = Aqk + (size_t)(m0 + arow) * (2 * EMB) + ah * 32;
        const __nv_bfloat16* bgp = Bqk + (size_t)(n0 + brow) * (2 * EMB) + bq * 16;

        // stage: [Ah | Al | Bh | Bl]
#define LOAD_QK(bufi, k0v) do { \
        const uint32_t sb = sbase + (bufi) * QSTG; \
        const __nv_bfloat16* _a = agp + (k0v); \
        CPASYNC16(sb + adst,      _a);      CPASYNC16(sb + adst + 16, _a + 8); \
        CPASYNC16(sb + adst + 32, _a + 16); CPASYNC16(sb + adst + 48, _a + 24); \
        const __nv_bfloat16* _al = _a + EMB; \
        CPASYNC16(sb + PC128 + adst,      _al);      CPASYNC16(sb + PC128 + adst + 16, _al + 8); \
        CPASYNC16(sb + PC128 + adst + 32, _al + 16); CPASYNC16(sb + PC128 + adst + 48, _al + 24); \
        const __nv_bfloat16* _b = bgp + (k0v); \
        CPASYNC16(sb + 2*PC128 + bdst, _b);          CPASYNC16(sb + 2*PC128 + bdst + 16, _b + 8); \
        const __nv_bfloat16* _bl = _b + EMB; \
        CPASYNC16(sb + 2*PC128 + PC64 + bdst, _bl);  CPASYNC16(sb + 2*PC128 + PC64 + bdst + 16, _bl + 8); \
    } while (0)

        LOAD_QK(0, 0); CP_COMMIT();

        #pragma unroll 1
        for (int it = 0; it < 6; it++) {
            CP_WAIT0();
            __syncthreads();
            if (it + 1 < 6) { LOAD_QK((it + 1) & 1, (it + 1) * 64); CP_COMMIT(); }

            const uint32_t sb = sbase + (it & 1) * QSTG;
            const uint32_t sAh = sb, sAl = sb + PC128;
            const uint32_t sBh = sb + 2 * PC128, sBl = sBh + PC64;
            #pragma unroll
            for (int kk = 0; kk < 4; kk++) {
                uint32_t ahf[4][4], alf[4][4], bh[4], bl[4];
                #pragma unroll
                for (int mi = 0; mi < 4; mi++)
                    LDSM4(ahf[mi], sAh + a_off + mi * (16 * 144) + kk * 32);
                LDSM4(bh, sBh + b_off + kk * 32);
                LDSM4(bl, sBl + b_off + kk * 32);
                #pragma unroll
                for (int mi = 0; mi < 4; mi++)
                    LDSM4(alf[mi], sAl + a_off + mi * (16 * 144) + kk * 32);
                #pragma unroll
                for (int mi = 0; mi < 4; mi++)
                    #pragma unroll
                    for (int sub = 0; sub < 2; sub++)
                        MMA_BF16(d[mi][sub], ahf[mi], bh[sub*2], bh[sub*2+1]);
                #pragma unroll
                for (int mi = 0; mi < 4; mi++)
                    #pragma unroll
                    for (int sub = 0; sub < 2; sub++)
                        MMA_BF16(d[mi][sub], ahf[mi], bl[sub*2], bl[sub*2+1]);
                #pragma unroll
                for (int mi = 0; mi < 4; mi++)
                    #pragma unroll
                    for (int sub = 0; sub < 2; sub++)
                        MMA_BF16(d[mi][sub], alf[mi], bh[sub*2], bh[sub*2+1]);
            }
        }
#undef LOAD_QK

        #pragma unroll
        for (int mi = 0; mi < 4; mi++) {
            int row0 = m0 + wm * 64 + mi * 16 + (lane >> 2);
            #pragma unroll
            for (int ni = 0; ni < 2; ni++) {
                int col = n0 + wn * 16 + ni * 8 + (lane & 3) * 2;
                *(float2*)(out_qk + (size_t)row0 * (2 * EMB) + col)       = make_float2(d[mi][ni][0], d[mi][ni][1]);
                *(float2*)(out_qk + (size_t)(row0 + 8) * (2 * EMB) + col) = make_float2(d[mi][ni][2], d[mi][ni][3]);
            }
        }
    } else {
        const int n0 = (blockIdx.x - 12) * 64;
        const __half* agp = Av + (size_t)(m0 + arow) * EMB + ah * 32;
        const __half* bgp = Bv + (size_t)(n0 + brow) * EMB + bq * 16;

#define LOAD_V(bufi, k0v) do { \
        const uint32_t sb = sbase + (bufi) * VSTG; \
        const __half* _a = agp + (k0v); \
        CPASYNC16(sb + adst,      _a);      CPASYNC16(sb + adst + 16, _a + 8); \
        CPASYNC16(sb + adst + 32, _a + 16); CPASYNC16(sb + adst + 48, _a + 24); \
        const __half* _b = bgp + (k0v); \
        CPASYNC16(sb + PC128 + bdst, _b);   CPASYNC16(sb + PC128 + bdst + 16, _b + 8); \
    } while (0)

        LOAD_V(0, 0);  CP_COMMIT();
        LOAD_V(1, 64); CP_COMMIT();

        #pragma unroll 1
        for (int it = 0; it < 6; it++) {
            CP_WAIT1();
            __syncthreads();
            if (it + 2 < 6) LOAD_V((it + 2) % 3, (it + 2) * 64);
            CP_COMMIT();

            const uint32_t sA = sbase + (it % 3) * VSTG;
            const uint32_t sB = sA + PC128;
            #pragma unroll
            for (int kk = 0; kk < 4; kk++) {
                uint32_t a[4][4], b[4];
                #pragma unroll
                for (int mi = 0; mi < 4; mi++)
                    LDSM4(a[mi], sA + a_off + mi * (16 * 144) + kk * 32);
                LDSM4(b, sB + b_off + kk * 32);
                #pragma unroll
                for (int mi = 0; mi < 4; mi++)
                    #pragma unroll
                    for (int sub = 0; sub < 2; sub++)
                        MMA_FP16(d[mi][sub], a[mi], b[sub*2], b[sub*2+1]);
            }
        }
#undef LOAD_V

        #pragma unroll
        for (int mi = 0; mi < 4; mi++) {
            int row0 = m0 + wm * 64 + mi * 16 + (lane >> 2);
            #pragma unroll
            for (int ni = 0; ni < 2; ni++) {
                int col = n0 + wn * 16 + ni * 8 + (lane & 3) * 2;
                *(__half2*)(out_v + (size_t)row0 * EMB + col) =
                    __floats2half2_rn(d[mi][ni][0], d[mi][ni][1]);
                *(__half2*)(out_v + (size_t)(row0 + 8) * EMB + col) =
                    __floats2half2_rn(d[mi][ni][2], d[mi][ni][3]);
            }
        }
    }
}

// ---------------- attention (q,k fp32; v fp16) ----------------
__global__ void __launch_bounds__(128)
attn_kernel(const float* __restrict__ qk, const __half* __restrict__ vh,
            __half* __restrict__ out) {
    const int b = blockIdx.x, h = blockIdx.y;
    const int tid = threadIdx.x;
    const int r = tid >> 1, half = tid & 1;
    __shared__ float ks[SEQ][HSZ];
    __shared__ float vs[SEQ][HSZ];

    for (int i = tid; i < SEQ * (HSZ / 4); i += 128) {
        int s = i / (HSZ / 4), c = i % (HSZ / 4);
        const float* ksrc = qk + (size_t)(b * SEQ + s) * (2 * EMB) + EMB + h * HSZ;
        *(float4*)&ks[s][c * 4] = *(const float4*)(ksrc + c * 4);
        const __half2* vsrc = (const __half2*)(vh + (size_t)(b * SEQ + s) * EMB + h * HSZ);
        float2 f0 = __half22float2(vsrc[c * 2]);
        float2 f1 = __half22float2(vsrc[c * 2 + 1]);
        *(float4*)&vs[s][c * 4] = make_float4(f0.x, f0.y, f1.x, f1.y);
    }
    u64 q2[12];
    {
        const float* qsrc = qk + (size_t)(b * SEQ + r) * (2 * EMB) + h * HSZ + half * 24;
        #pragma unroll
        for (int i = 0; i < 6; i++) {
            float4 v = *(const float4*)(qsrc + 4 * i);
            q2[2 * i]     = pk2(v.x, v.y);
            q2[2 * i + 1] = pk2(v.z, v.w);
        }
    }
    __syncthreads();

    const uint32_t pmask = 3u << ((tid & 31) & ~1);
    float m = -1e30f, l = 0.0f;
    u64 o2[12];
    #pragma unroll
    for (int i = 0; i < 12; i++) o2[i] = 0ull;

    for (int s0 = 0; s0 <= r; s0 += 16) {
        float sc[16];
        float bm = -1e30f;
        #pragma unroll
        for (int j = 0; j < 16; j++) {
            int s = s0 + j;
            float pd = 0.0f;
            if (s <= r) {
                const u64* kp2 = (const u64*)&ks[s][half * 24];
                u64 acc = 0ull;
                #pragma unroll
                for (int i = 0; i < 12; i++) FMA2(acc, q2[i], kp2[i]);
                float2 ac = upk2(acc);
                pd = ac.x + ac.y;
            }
            pd += __shfl_xor_sync(pmask, pd, 1);
            sc[j] = (s <= r) ? pd * ATT_SCALE : -1e30f;
            bm = fmaxf(bm, sc[j]);
        }
        float nm = fmaxf(m, bm);
        float alpha = __expf(m - nm);
        l *= alpha;
        u64 a2 = pk2(alpha, alpha);
        #pragma unroll
        for (int i = 0; i < 12; i++) { u64 t; MUL2(t, o2[i], a2); o2[i] = t; }
        #pragma unroll
        for (int j = 0; j < 16; j++) {
            float p = __expf(sc[j] - nm);
            l += p;
            int sv = s0 + j; sv = sv < SEQ ? sv : SEQ - 1;
            const u64* vp2 = (const u64*)&vs[sv][half * 24];
            u64 p2v = pk2(p, p);
            #pragma unroll
            for (int i = 0; i < 12; i++) FMA2(o2[i], p2v, vp2[i]);
        }
        m = nm;
    }
    float inv = 1.0f / l;
    __half* op = out + (size_t)(b * SEQ + r) * EMB + h * HSZ + half * 24;
    #pragma unroll
    for (int i = 0; i < 12; i++) {
        float2 f = upk2(o2[i]);
        *(__half2*)(op + 2 * i) = __floats2half2_rn(f.x * inv, f.y * inv);
    }
}

// ---------------- launch ----------------
extern "C" void kernel_launch(void* const* d_in, const int* in_sizes, int n_in,
                              void* d_out, int out_size) {
    const float* x     = (const float*)d_in[0];
    const float* ln1_g = (const float*)d_in[1];
    const float* ln1_b = (const float*)d_in[2];
    const float* ln2_g = (const float*)d_in[3];
    const float* ln2_b = (const float*)d_in[4];
    const float* Wq    = (const float*)d_in[5];
    const float* Wk    = (const float*)d_in[6];
    const float* Wv    = (const float*)d_in[7];
    const float* Wp    = (const float*)d_in[8];
    const float* bp    = (const float*)d_in[9];
    const float* W1    = (const float*)d_in[10];
    const float* b1    = (const float*)d_in[11];
    const float* W2    = (const float*)d_in[12];
    const float* b2    = (const float*)d_in[13];
    float* out = (float*)d_out;

    __nv_bfloat16 *ln1, *wqk;
    __half *h1h, *vhp, *attnh, *h2h, *hidh, *wvh, *wph, *w1h, *w2h;
    float *qkp, *x2;
    cudaGetSymbolAddress((void**)&ln1,   g_ln1);
    cudaGetSymbolAddress((void**)&h1h,   g_h1h);
    cudaGetSymbolAddress((void**)&qkp,   g_qk);
    cudaGetSymbolAddress((void**)&vhp,   g_vh);
    cudaGetSymbolAddress((void**)&attnh, g_attnh);
    cudaGetSymbolAddress((void**)&x2,    g_x2);
    cudaGetSymbolAddress((void**)&h2h,   g_h2h);
    cudaGetSymbolAddress((void**)&hidh,  g_hidh);
    cudaGetSymbolAddress((void**)&wqk,   g_wqk);
    cudaGetSymbolAddress((void**)&wvh,   g_wvh);
    cudaGetSymbolAddress((void**)&wph,   g_wph);
    cudaGetSymbolAddress((void**)&w1h,   g_w1h);
    cudaGetSymbolAddress((void**)&w2h,   g_w2h);

    cudaFuncSetAttribute(gemm_qkv,       cudaFuncAttributeMaxDynamicSharedMemorySize, GSMEMQ);
    cudaFuncSetAttribute((gemm16<3,6>),  cudaFuncAttributeMaxDynamicSharedMemorySize, GSMEM2);
    cudaFuncSetAttribute((gemm16<2,6>),  cudaFuncAttributeMaxDynamicSharedMemorySize, GSMEM2);
    cudaFuncSetAttribute((gemm16<1,24>), cudaFuncAttributeMaxDynamicSharedMemorySize, GSMEM2);

    // 1) LN1 (bf16 split + fp16) + all weight prep + sem zero
    stage1_kernel<<<LN_BLOCKS + PREP_BLOCKS, 128>>>(x, ln1_g, ln1_b, ln1, h1h,
                                                    Wq, Wk, Wv, Wp, W1, W2);
    // 2) fat QKV: QK (3-pass bf16, 12 n-blocks of 64) + V (1-pass fp16, 6 n-blocks)
    gemm_qkv<<<dim3(18, N_TOK / 128), 256, GSMEMQ>>>(ln1, wqk, h1h, wvh, qkp, vhp);
    // 3) attention -> fp16
    attn_kernel<<<dim3(2048, NHEAD), 128>>>(qkp, vhp, attnh);
    // 4) proj + bias + residual(x) -> fp32 x2, with fused LN2 -> h2h
    gemm16<3,6><<<dim3(3, N_TOK / 128), 256, GSMEM2>>>(attnh, wph, bp, x, x2, EMB,
                                                       ln2_g, ln2_b, h2h);
    // 5) MLP up + relu -> fp16 hidden
    gemm16<2,6><<<dim3(12, N_TOK / 128), 256, GSMEM2>>>(h2h, w1h, b1, nullptr, hidh, FF,
                                                        nullptr, nullptr, nullptr);
    // 6) MLP down (K=1536) + bias + residual(x2) -> out
    gemm16<1,24><<<dim3(3, N_TOK / 128), 256, GSMEM2>>>(hidh, w2h, b2, x2, out, EMB,
                                                        nullptr, nullptr, nullptr);
}

// round 15
// speedup vs baseline: 1.0535x; 1.0535x over previous
#include <cuda_runtime.h>
#include <cuda_bf16.h>
#include <cuda_fp16.h>
#include <cstdint>

// ---------------- problem constants ----------------
constexpr int N_TOK  = 2048 * 64;   // 131072 tokens
constexpr int EMB    = 384;
constexpr int NHEAD  = 8;
constexpr int HSZ    = 48;
constexpr int SEQ    = 64;
constexpr int FF     = 1536;
constexpr float ATT_SCALE = 2.449489742783178f;

// ---------------- scratch (static device memory) ----------------
__device__ __align__(128) __nv_bfloat16 g_ln1 [(size_t)N_TOK * 2 * EMB];    // [hi|lo] for QK
__device__ __align__(128) __half        g_h1h [(size_t)N_TOK * EMB];        // fp16 LN1 (for V)
__device__ __align__(128) float         g_qk  [(size_t)N_TOK * 2 * EMB];    // fp32 q|k
__device__ __align__(128) __half        g_vh  [(size_t)N_TOK * EMB];        // fp16 v
__device__ __align__(128) __half        g_attnh[(size_t)N_TOK * EMB];       // fp16
__device__ __align__(128) float         g_x2  [(size_t)N_TOK * EMB];        // fp32 residual
__device__ __align__(128) __half        g_h2h [(size_t)N_TOK * EMB];        // fp16
__device__ __align__(128) __half        g_hidh[(size_t)N_TOK * FF];         // fp16
__device__ __align__(128) __nv_bfloat16 g_wqk [(size_t)(2*EMB) * 2 * EMB];  // [768][hi|lo 768]
__device__ __align__(128) __half        g_wvh [(size_t)EMB * EMB];          // [N][K] fp16
__device__ __align__(128) __half        g_wph [(size_t)EMB * EMB];
__device__ __align__(128) __half        g_w1h [(size_t)FF  * EMB];
__device__ __align__(128) __half        g_w2h [(size_t)EMB * FF];
__device__ int g_sem[N_TOK / 128];   // proj->LN2 fusion semaphores

// ---------------- PTX helpers ----------------
typedef unsigned long long u64;
__device__ __forceinline__ uint32_t smem_u32(const void* p) {
    uint32_t a;
    asm("{ .reg .u64 t; cvta.to.shared.u64 t, %1; cvt.u32.u64 %0, t; }" : "=r"(a) : "l"(p));
    return a;
}
#define CPASYNC16(dst, src) asm volatile("cp.async.cg.shared.global [%0], [%1], 16;" :: "r"(dst), "l"(src) : "memory")
#define CP_COMMIT()         asm volatile("cp.async.commit_group;" ::: "memory")
#define CP_WAIT1()          asm volatile("cp.async.wait_group 1;" ::: "memory")
#define CP_WAIT0()          asm volatile("cp.async.wait_group 0;" ::: "memory")

#define LDSM4(r, addr) \
    asm volatile("ldmatrix.sync.aligned.m8n8.x4.shared.b16 {%0,%1,%2,%3}, [%4];" \
        : "=r"((r)[0]), "=r"((r)[1]), "=r"((r)[2]), "=r"((r)[3]) : "r"(addr))

#define MMA_BF16(d, a, b0, b1) \
    asm volatile("mma.sync.aligned.m16n8k16.row.col.f32.bf16.bf16.f32 " \
        "{%0,%1,%2,%3}, {%4,%5,%6,%7}, {%8,%9}, {%0,%1,%2,%3};" \
        : "+f"((d)[0]), "+f"((d)[1]), "+f"((d)[2]), "+f"((d)[3]) \
        : "r"((a)[0]), "r"((a)[1]), "r"((a)[2]), "r"((a)[3]), "r"(b0), "r"(b1))

#define MMA_FP16(d, a, b0, b1) \
    asm volatile("mma.sync.aligned.m16n8k16.row.col.f32.f16.f16.f32 " \
        "{%0,%1,%2,%3}, {%4,%5,%6,%7}, {%8,%9}, {%0,%1,%2,%3};" \
        : "+f"((d)[0]), "+f"((d)[1]), "+f"((d)[2]), "+f"((d)[3]) \
        : "r"((a)[0]), "r"((a)[1]), "r"((a)[2]), "r"((a)[3]), "r"(b0), "r"(b1))

__device__ __forceinline__ u64 pk2(float lo, float hi) {
    u64 r; asm("mov.b64 %0, {%1, %2};" : "=l"(r) : "f"(lo), "f"(hi)); return r;
}
__device__ __forceinline__ float2 upk2(u64 p) {
    float2 r; asm("mov.b64 {%0, %1}, %2;" : "=f"(r.x), "=f"(r.y) : "l"(p)); return r;
}
#define FMA2(d, a, b) asm("fma.rn.f32x2 %0, %1, %2, %0;" : "+l"(d) : "l"(a), "l"(b))
#define MUL2(d, a, b) asm("mul.rn.f32x2 %0, %1, %2;" : "=l"(d) : "l"(a), "l"(b))

__device__ __forceinline__ __nv_bfloat16 bf_hi(float v) { return __float2bfloat16(v); }
__device__ __forceinline__ __nv_bfloat16 bf_lo(float v, __nv_bfloat16 hi) {
    return __float2bfloat16(v - __bfloat162float(hi));
}

// ---------------- stage 1: LN1 fused with ALL weight prep (+sem zero) ----------------
constexpr int LN_BLOCKS   = N_TOK / 4;
constexpr int PREP_TOTAL  = 147456 + 147456 + 589824 + 589824;
constexpr int PREP_BLOCKS = PREP_TOTAL / 512;

__global__ void __launch_bounds__(128)
stage1_kernel(const float* __restrict__ in, const float* __restrict__ g,
              const float* __restrict__ b, __nv_bfloat16* __restrict__ bfout,
              __half* __restrict__ hout,
              const float* __restrict__ Wq, const float* __restrict__ Wk,
              const float* __restrict__ Wv, const float* __restrict__ Wp,
              const float* __restrict__ W1, const float* __restrict__ W2) {
    if (blockIdx.x < 8) {
        int i = blockIdx.x * 128 + threadIdx.x;
        if (i < N_TOK / 128) g_sem[i] = 0;
    }
    if (blockIdx.x < LN_BLOCKS) {
        const int row = blockIdx.x * 4 + (threadIdx.x >> 5);
        const int lane = threadIdx.x & 31;
        const float* rp = in + (size_t)row * EMB + lane * 12;
        float4 v0 = *(const float4*)(rp), v1 = *(const float4*)(rp + 4), v2 = *(const float4*)(rp + 8);
        float vv[12] = {v0.x, v0.y, v0.z, v0.w, v1.x, v1.y, v1.z, v1.w, v2.x, v2.y, v2.z, v2.w};
        float s = 0.0f, ss = 0.0f;
        #pragma unroll
        for (int i = 0; i < 12; i++) { s += vv[i]; ss += vv[i] * vv[i]; }
        #pragma unroll
        for (int off = 16; off > 0; off >>= 1) {
            s  += __shfl_xor_sync(0xffffffffu, s, off);
            ss += __shfl_xor_sync(0xffffffffu, ss, off);
        }
        float mu = s * (1.0f / EMB);
        float var = ss * (1.0f / EMB) - mu * mu;
        float rs = rsqrtf(var + 1e-5f);
        const float* gp = g + lane * 12;
        const float* bp = b + lane * 12;
        float o[12];
        #pragma unroll
        for (int i = 0; i < 12; i++) o[i] = (vv[i] - mu) * rs * gp[i] + bp[i];
        __half hh[12];
        #pragma unroll
        for (int i = 0; i < 12; i++) hh[i] = __float2half(o[i]);
        __half* hrow = hout + (size_t)row * EMB + lane * 12;
        *(uint2*)(hrow)     = *(uint2*)(hh);
        *(uint2*)(hrow + 4) = *(uint2*)(hh + 4);
        *(uint2*)(hrow + 8) = *(uint2*)(hh + 8);
        __nv_bfloat16 hi[12], lo[12];
        #pragma unroll
        for (int i = 0; i < 12; i++) { hi[i] = bf_hi(o[i]); lo[i] = bf_lo(o[i], hi[i]); }
        __nv_bfloat16* orow = bfout + (size_t)row * 2 * EMB + lane * 12;
        *(uint2*)(orow)     = *(uint2*)(hi);
        *(uint2*)(orow + 4) = *(uint2*)(hi + 4);
        *(uint2*)(orow + 8) = *(uint2*)(hi + 8);
        __nv_bfloat16* lrow = orow + EMB;
        *(uint2*)(lrow)     = *(uint2*)(lo);
        *(uint2*)(lrow + 4) = *(uint2*)(lo + 4);
        *(uint2*)(lrow + 8) = *(uint2*)(lo + 8);
    } else {
        int base = (blockIdx.x - LN_BLOCKS) * 512 + threadIdx.x * 4;
        #pragma unroll
        for (int e = 0; e < 4; e++) {
            int i = base + e;
            if (i < 147456) {
                int h = i / (EMB * HSZ), r = i % (EMB * HSZ), c = r / HSZ, d = r % HSZ;
                int n = h * HSZ + d;
                float q = Wq[i], k = Wk[i];
                __nv_bfloat16 qh = bf_hi(q), kh = bf_hi(k);
                size_t rq = (size_t)n * 2 * EMB, rk = (size_t)(EMB + n) * 2 * EMB;
                g_wqk[rq + c] = qh;  g_wqk[rq + EMB + c] = bf_lo(q, qh);
                g_wqk[rk + c] = kh;  g_wqk[rk + EMB + c] = bf_lo(k, kh);
                g_wvh[(size_t)n * EMB + c] = __float2half(Wv[i]);
            } else if (i < 294912) {
                int j = i - 147456;
                int k = j / EMB, n = j % EMB;
                g_wph[(size_t)n * EMB + k] = __float2half(Wp[j]);
            } else if (i < 884736) {
                int j = i - 294912;
                int k = j / FF, n = j % FF;
                g_w1h[(size_t)n * EMB + k] = __float2half(W1[j]);
            } else {
                int j = i - 884736;
                int k = j / EMB, n = j % EMB;
                g_w2h[(size_t)n * FF + k] = __float2half(W2[j]);
            }
        }
    }
}

// ---------------- tiling constants ----------------
constexpr int PC128  = 128 * 144;
constexpr int PC256  = 256 * 144;
constexpr int FSTG2  = 2 * PC128;                 // 36864 (fp16 stage)
constexpr int GSMEM2 = 3 * FSTG2;                 // 110592 -> 2 CTAs/SM
constexpr int VSTG   = PC256 + PC128;             // 55296
constexpr int QSTG   = 2 * PC256 + 2 * PC128;     // 110592
constexpr int GSMEMQ = 2 * QSTG;                  // 221184

// ================= fp16 GEMM: 256 thr, BM=128/BN=128, warp tile 64x32, 2 CTA/SM =================
// MODE 1: fp32=acc+bias+res   2: fp16=relu(acc+bias)   3: MODE1 + fused LN2 (proj)
template<int MODE, int KST>
__global__ void __launch_bounds__(256, 2)
gemm16(const __half* __restrict__ A, const __half* __restrict__ B,
       const float* __restrict__ bias, const float* __restrict__ res,
       void* __restrict__ out, int Ntot,
       const float* __restrict__ g2, const float* __restrict__ b2v,
       __half* __restrict__ h2out) {
    extern __shared__ char smem[];
    const uint32_t sbase = smem_u32(smem);
    const int tid = threadIdx.x, lane = tid & 31, wid = tid >> 5;
    const int wm = wid >> 2, wn = wid & 3;
    const int m0 = blockIdx.y * 128, n0 = blockIdx.x * 128;
    constexpr int Kw = KST * 64;

    const int lrow = tid >> 1, lh = tid & 1;
    const __half* agp = A + (size_t)(m0 + lrow) * Kw + lh * 32;
    const __half* bgp = B + (size_t)(n0 + lrow) * Kw + lh * 32;
    const uint32_t ldst = (uint32_t)(lrow * 144 + lh * 64);

#define LOAD_F(bufi, k0v) do { \
        const uint32_t sb = sbase + (bufi) * FSTG2; \
        const __half* _a = agp + (k0v); \
        CPASYNC16(sb + ldst,      _a);      CPASYNC16(sb + ldst + 16, _a + 8); \
        CPASYNC16(sb + ldst + 32, _a + 16); CPASYNC16(sb + ldst + 48, _a + 24); \
        const __half* _b = bgp + (k0v); \
        CPASYNC16(sb + PC128 + ldst,      _b);      CPASYNC16(sb + PC128 + ldst + 16, _b + 8); \
        CPASYNC16(sb + PC128 + ldst + 32, _b + 16); CPASYNC16(sb + PC128 + ldst + 48, _b + 24); \
    } while (0)

    float d[4][4][4];
    #pragma unroll
    for (int i = 0; i < 4; i++)
        #pragma unroll
        for (int j = 0; j < 4; j++)
            #pragma unroll
            for (int q = 0; q < 4; q++) d[i][j][q] = 0.0f;

    const uint32_t a_off = (uint32_t)((wm * 64 + (lane & 15)) * 144 + (lane >> 4) * 16);
    const int nl = (lane & 7) + ((lane >> 4) << 3);
    const int kc = (lane >> 3) & 1;
    const uint32_t b_off = (uint32_t)((wn * 32 + nl) * 144 + kc * 16);

    LOAD_F(0, 0);  CP_COMMIT();
    LOAD_F(1, 64); CP_COMMIT();

    for (int it = 0; it < KST; it++) {
        CP_WAIT1();
        __syncthreads();
        if (it + 2 < KST) LOAD_F((it + 2) % 3, (it + 2) * 64);
        CP_COMMIT();

        const uint32_t sA = sbase + (it % 3) * FSTG2;
        const uint32_t sB = sA + PC128;
        #pragma unroll
        for (int kk = 0; kk < 4; kk++) {
            uint32_t a[4][4], b[2][4];
            #pragma unroll
            for (int mi = 0; mi < 4; mi++)
                LDSM4(a[mi], sA + a_off + mi * (16 * 144) + kk * 32);
            #pragma unroll
            for (int np = 0; np < 2; np++)
                LDSM4(b[np], sB + b_off + np * (16 * 144) + kk * 32);
            #pragma unroll
            for (int mi = 0; mi < 4; mi++)
                #pragma unroll
                for (int np = 0; np < 2; np++)
                    #pragma unroll
                    for (int sub = 0; sub < 2; sub++)
                        MMA_FP16(d[mi][np * 2 + sub], a[mi], b[np][sub*2], b[np][sub*2+1]);
        }
    }
#undef LOAD_F

    #pragma unroll
    for (int mi = 0; mi < 4; mi++) {
        int row0 = m0 + wm * 64 + mi * 16 + (lane >> 2);
        #pragma unroll
        for (int ni = 0; ni < 4; ni++) {
            int col = n0 + wn * 32 + ni * 8 + (lane & 3) * 2;
            if (MODE == 1 || MODE == 3) {
                float b0 = bias[col], b1 = bias[col + 1];
                float* o = (float*)out;
                float2 r0 = *(const float2*)(res + (size_t)row0 * Ntot + col);
                float2 r1 = *(const float2*)(res + (size_t)(row0 + 8) * Ntot + col);
                *(float2*)(o + (size_t)row0 * Ntot + col) =
                    make_float2(d[mi][ni][0] + b0 + r0.x, d[mi][ni][1] + b1 + r0.y);
                *(float2*)(o + (size_t)(row0 + 8) * Ntot + col) =
                    make_float2(d[mi][ni][2] + b0 + r1.x, d[mi][ni][3] + b1 + r1.y);
            } else {
                float b0 = bias[col], b1 = bias[col + 1];
                __half* ob = (__half*)out;
                *(__half2*)(ob + (size_t)row0 * Ntot + col) =
                    __floats2half2_rn(fmaxf(d[mi][ni][0] + b0, 0.0f), fmaxf(d[mi][ni][1] + b1, 0.0f));
                *(__half2*)(ob + (size_t)(row0 + 8) * Ntot + col) =
                    __floats2half2_rn(fmaxf(d[mi][ni][2] + b0, 0.0f), fmaxf(d[mi][ni][3] + b1, 0.0f));
            }
        }
    }

    if (MODE == 3) {
        __threadfence();
        __syncthreads();
        __shared__ int elect;
        if (tid == 0) {
            int old = atomicAdd(&g_sem[blockIdx.y], 1);
            elect = (old == 2);
        }
        __syncthreads();
        if (elect) {
            __threadfence();
            const float* x2f = (const float*)out;
            const int lane_ = tid & 31, wrp = tid >> 5;
            for (int rr = wrp; rr < 128; rr += 8) {
                int row = m0 + rr;
                const float* rp = x2f + (size_t)row * EMB + lane_ * 12;
                float4 v0 = *(const float4*)(rp), v1 = *(const float4*)(rp + 4), v2 = *(const float4*)(rp + 8);
                float vv[12] = {v0.x, v0.y, v0.z, v0.w, v1.x, v1.y, v1.z, v1.w, v2.x, v2.y, v2.z, v2.w};
                float s = 0.0f, ss = 0.0f;
                #pragma unroll
                for (int i = 0; i < 12; i++) { s += vv[i]; ss += vv[i] * vv[i]; }
                #pragma unroll
                for (int off = 16; off > 0; off >>= 1) {
                    s  += __shfl_xor_sync(0xffffffffu, s, off);
                    ss += __shfl_xor_sync(0xffffffffu, ss, off);
                }
                float mu = s * (1.0f / EMB);
                float var = ss * (1.0f / EMB) - mu * mu;
                float rs = rsqrtf(var + 1e-5f);
                const float* gp = g2 + lane_ * 12;
                const float* bp = b2v + lane_ * 12;
                __half hh[12];
                #pragma unroll
                for (int i = 0; i < 12; i++) hh[i] = __float2half((vv[i] - mu) * rs * gp[i] + bp[i]);
                __half* hrow = h2out + (size_t)row * EMB + lane_ * 12;
                *(uint2*)(hrow)     = *(uint2*)(hh);
                *(uint2*)(hrow + 4) = *(uint2*)(hh + 4);
                *(uint2*)(hrow + 8) = *(uint2*)(hh + 8);
            }
        }
    }
}

// ================= fat QKV kernel: BM=256, 512 thr, warp tile 64x32 =================
// blockIdx.x < 6: QK 3-pass bf16 -> fp32 qk buffer; >= 6: V 1-pass fp16 -> fp16 v buffer.
__global__ void __launch_bounds__(512, 1)
gemm_qkv(const __nv_bfloat16* __restrict__ Aqk, const __nv_bfloat16* __restrict__ Bqk,
         const __half* __restrict__ Av, const __half* __restrict__ Bv,
         float* __restrict__ out_qk, __half* __restrict__ out_v) {
    extern __shared__ char smem[];
    const uint32_t sbase = smem_u32(smem);
    const int tid = threadIdx.x, lane = tid & 31, wid = tid >> 5;
    const int wm = wid >> 2, wn = wid & 3;
    const int m0 = blockIdx.y * 256;
    const int arow = tid >> 1, ah = tid & 1;
    const int brow = tid >> 2, bq = tid & 3;
    const uint32_t adst = (uint32_t)(arow * 144 + ah * 64);
    const uint32_t bdst = (uint32_t)(brow * 144 + bq * 32);
    const uint32_t a_off = (uint32_t)((wm * 64 + (lane & 15)) * 144 + (lane >> 4) * 16);
    const int nl = (lane & 7) + ((lane >> 4) << 3);
    const int kc = (lane >> 3) & 1;
    const uint32_t b_off = (uint32_t)((wn * 32 + nl) * 144 + kc * 16);

    float d[4][4][4];
    #pragma unroll
    for (int i = 0; i < 4; i++)
        #pragma unroll
        for (int j = 0; j < 4; j++)
            #pragma unroll
            for (int q = 0; q < 4; q++) d[i][j][q] = 0.0f;

    if (blockIdx.x < 6) {
        const int n0 = blockIdx.x * 128;
        const __nv_bfloat16* agp = Aqk + (size_t)(m0 + arow) * (2 * EMB) + ah * 32;
        const __nv_bfloat16* bgp = Bqk + (size_t)(n0 + brow) * (2 * EMB) + bq * 16;

#define LOAD_QK(bufi, k0v) do { \
        const uint32_t sb = sbase + (bufi) * QSTG; \
        const __nv_bfloat16* _a = agp + (k0v); \
        CPASYNC16(sb + adst,      _a);      CPASYNC16(sb + adst + 16, _a + 8); \
        CPASYNC16(sb + adst + 32, _a + 16); CPASYNC16(sb + adst + 48, _a + 24); \
        const __nv_bfloat16* _al = _a + EMB; \
        CPASYNC16(sb + PC256 + adst,      _al);      CPASYNC16(sb + PC256 + adst + 16, _al + 8); \
        CPASYNC16(sb + PC256 + adst + 32, _al + 16); CPASYNC16(sb + PC256 + adst + 48, _al + 24); \
        const __nv_bfloat16* _b = bgp + (k0v); \
        CPASYNC16(sb + 2*PC256 + bdst, _b);            CPASYNC16(sb + 2*PC256 + bdst + 16, _b + 8); \
        CPASYNC16(sb + 2*PC256 + PC128 + bdst, _b + EMB); \
        CPASYNC16(sb + 2*PC256 + PC128 + bdst + 16, _b + EMB + 8); \
    } while (0)

        LOAD_QK(0, 0); CP_COMMIT();

        #pragma unroll 1
        for (int it = 0; it < 6; it++) {
            CP_WAIT0();
            __syncthreads();
            if (it + 1 < 6) { LOAD_QK((it + 1) & 1, (it + 1) * 64); CP_COMMIT(); }

            const uint32_t sb = sbase + (it & 1) * QSTG;
            const uint32_t sAh = sb, sAl = sb + PC256;
            const uint32_t sBh = sb + 2 * PC256, sBl = sBh + PC128;
            #pragma unroll
            for (int kk = 0; kk < 4; kk++) {
                uint32_t ahf[4][4], alf[4][4], bh[2][4], bl[2][4];
                #pragma unroll
                for (int mi = 0; mi < 4; mi++)
                    LDSM4(ahf[mi], sAh + a_off + mi * (16 * 144) + kk * 32);
                #pragma unroll
                for (int np = 0; np < 2; np++) {
                    LDSM4(bh[np], sBh + b_off + np * (16 * 144) + kk * 32);
                    LDSM4(bl[np], sBl + b_off + np * (16 * 144) + kk * 32);
                }
                #pragma unroll
                for (int mi = 0; mi < 4; mi++)
                    LDSM4(alf[mi], sAl + a_off + mi * (16 * 144) + kk * 32);
                #pragma unroll
                for (int mi = 0; mi < 4; mi++)
                    #pragma unroll
                    for (int np = 0; np < 2; np++)
                        #pragma unroll
                        for (int sub = 0; sub < 2; sub++)
                            MMA_BF16(d[mi][np * 2 + sub], ahf[mi], bh[np][sub*2], bh[np][sub*2+1]);
                #pragma unroll
                for (int mi = 0; mi < 4; mi++)
                    #pragma unroll
                    for (int np = 0; np < 2; np++)
                        #pragma unroll
                        for (int sub = 0; sub < 2; sub++)
                            MMA_BF16(d[mi][np * 2 + sub], ahf[mi], bl[np][sub*2], bl[np][sub*2+1]);
                #pragma unroll
                for (int mi = 0; mi < 4; mi++)
                    #pragma unroll
                    for (int np = 0; np < 2; np++)
                        #pragma unroll
                        for (int sub = 0; sub < 2; sub++)
                            MMA_BF16(d[mi][np * 2 + sub], alf[mi], bh[np][sub*2], bh[np][sub*2+1]);
            }
        }
#undef LOAD_QK

        #pragma unroll
        for (int mi = 0; mi < 4; mi++) {
            int row0 = m0 + wm * 64 + mi * 16 + (lane >> 2);
            #pragma unroll
            for (int ni = 0; ni < 4; ni++) {
                int col = n0 + wn * 32 + ni * 8 + (lane & 3) * 2;
                *(float2*)(out_qk + (size_t)row0 * (2 * EMB) + col)       = make_float2(d[mi][ni][0], d[mi][ni][1]);
                *(float2*)(out_qk + (size_t)(row0 + 8) * (2 * EMB) + col) = make_float2(d[mi][ni][2], d[mi][ni][3]);
            }
        }
    } else {
        const int n0 = (blockIdx.x - 6) * 128;
        const __half* agp = Av + (size_t)(m0 + arow) * EMB + ah * 32;
        const __half* bgp = Bv + (size_t)(n0 + brow) * EMB + bq * 16;

#define LOAD_V(bufi, k0v) do { \
        const uint32_t sb = sbase + (bufi) * VSTG; \
        const __half* _a = agp + (k0v); \
        CPASYNC16(sb + adst,      _a);      CPASYNC16(sb + adst + 16, _a + 8); \
        CPASYNC16(sb + adst + 32, _a + 16); CPASYNC16(sb + adst + 48, _a + 24); \
        const __half* _b = bgp + (k0v); \
        CPASYNC16(sb + PC256 + bdst, _b);  CPASYNC16(sb + PC256 + bdst + 16, _b + 8); \
    } while (0)

        LOAD_V(0, 0);  CP_COMMIT();
        LOAD_V(1, 64); CP_COMMIT();

        #pragma unroll 1
        for (int it = 0; it < 6; it++) {
            CP_WAIT1();
            __syncthreads();
            if (it + 2 < 6) LOAD_V((it + 2) % 3, (it + 2) * 64);
            CP_COMMIT();

            const uint32_t sA = sbase + (it % 3) * VSTG;
            const uint32_t sB = sA + PC256;
            #pragma unroll
            for (int kk = 0; kk < 4; kk++) {
                uint32_t a[4][4], b[2][4];
                #pragma unroll
                for (int mi = 0; mi < 4; mi++)
                    LDSM4(a[mi], sA + a_off + mi * (16 * 144) + kk * 32);
                #pragma unroll
                for (int np = 0; np < 2; np++)
                    LDSM4(b[np], sB + b_off + np * (16 * 144) + kk * 32);
                #pragma unroll
                for (int mi = 0; mi < 4; mi++)
                    #pragma unroll
                    for (int np = 0; np < 2; np++)
                        #pragma unroll
                        for (int sub = 0; sub < 2; sub++)
                            MMA_FP16(d[mi][np * 2 + sub], a[mi], b[np][sub*2], b[np][sub*2+1]);
            }
        }
#undef LOAD_V

        #pragma unroll
        for (int mi = 0; mi < 4; mi++) {
            int row0 = m0 + wm * 64 + mi * 16 + (lane >> 2);
            #pragma unroll
            for (int ni = 0; ni < 4; ni++) {
                int col = n0 + wn * 32 + ni * 8 + (lane & 3) * 2;
                *(__half2*)(out_v + (size_t)row0 * EMB + col) =
                    __floats2half2_rn(d[mi][ni][0], d[mi][ni][1]);
                *(__half2*)(out_v + (size_t)(row0 + 8) * EMB + col) =
                    __floats2half2_rn(d[mi][ni][2], d[mi][ni][3]);
            }
        }
    }
}

// ---------------- attention (q,k fp32; v fp16) ----------------
__global__ void __launch_bounds__(128)
attn_kernel(const float* __restrict__ qk, const __half* __restrict__ vh,
            __half* __restrict__ out) {
    const int b = blockIdx.x, h = blockIdx.y;
    const int tid = threadIdx.x;
    const int r = tid >> 1, half = tid & 1;
    __shared__ float ks[SEQ][HSZ];
    __shared__ float vs[SEQ][HSZ];

    for (int i = tid; i < SEQ * (HSZ / 4); i += 128) {
        int s = i / (HSZ / 4), c = i % (HSZ / 4);
        const float* ksrc = qk + (size_t)(b * SEQ + s) * (2 * EMB) + EMB + h * HSZ;
        *(float4*)&ks[s][c * 4] = *(const float4*)(ksrc + c * 4);
        const __half2* vsrc = (const __half2*)(vh + (size_t)(b * SEQ + s) * EMB + h * HSZ);
        float2 f0 = __half22float2(vsrc[c * 2]);
        float2 f1 = __half22float2(vsrc[c * 2 + 1]);
        *(float4*)&vs[s][c * 4] = make_float4(f0.x, f0.y, f1.x, f1.y);
    }
    u64 q2[12];
    {
        const float* qsrc = qk + (size_t)(b * SEQ + r) * (2 * EMB) + h * HSZ + half * 24;
        #pragma unroll
        for (int i = 0; i < 6; i++) {
            float4 v = *(const float4*)(qsrc + 4 * i);
            q2[2 * i]     = pk2(v.x, v.y);
            q2[2 * i + 1] = pk2(v.z, v.w);
        }
    }
    __syncthreads();

    const uint32_t pmask = 3u << ((tid & 31) & ~1);
    float m = -1e30f, l = 0.0f;
    u64 o2[12];
    #pragma unroll
    for (int i = 0; i < 12; i++) o2[i] = 0ull;

    for (int s0 = 0; s0 <= r; s0 += 16) {
        float sc[16];
        float bm = -1e30f;
        #pragma unroll
        for (int j = 0; j < 16; j++) {
            int s = s0 + j;
            float pd = 0.0f;
            if (s <= r) {
                const u64* kp2 = (const u64*)&ks[s][half * 24];
                u64 acc = 0ull;
                #pragma unroll
                for (int i = 0; i < 12; i++) FMA2(acc, q2[i], kp2[i]);
                float2 ac = upk2(acc);
                pd = ac.x + ac.y;
            }
            pd += __shfl_xor_sync(pmask, pd, 1);
            sc[j] = (s <= r) ? pd * ATT_SCALE : -1e30f;
            bm = fmaxf(bm, sc[j]);
        }
        float nm = fmaxf(m, bm);
        float alpha = __expf(m - nm);
        l *= alpha;
        u64 a2 = pk2(alpha, alpha);
        #pragma unroll
        for (int i = 0; i < 12; i++) { u64 t; MUL2(t, o2[i], a2); o2[i] = t; }
        #pragma unroll
        for (int j = 0; j < 16; j++) {
            float p = __expf(sc[j] - nm);
            l += p;
            int sv = s0 + j; sv = sv < SEQ ? sv : SEQ - 1;
            const u64* vp2 = (const u64*)&vs[sv][half * 24];
            u64 p2v = pk2(p, p);
            #pragma unroll
            for (int i = 0; i < 12; i++) FMA2(o2[i], p2v, vp2[i]);
        }
        m = nm;
    }
    float inv = 1.0f / l;
    __half* op = out + (size_t)(b * SEQ + r) * EMB + h * HSZ + half * 24;
    #pragma unroll
    for (int i = 0; i < 12; i++) {
        float2 f = upk2(o2[i]);
        *(__half2*)(op + 2 * i) = __floats2half2_rn(f.x * inv, f.y * inv);
    }
}

// ---------------- launch ----------------
extern "C" void kernel_launch(void* const* d_in, const int* in_sizes, int n_in,
                              void* d_out, int out_size) {
    const float* x     = (const float*)d_in[0];
    const float* ln1_g = (const float*)d_in[1];
    const float* ln1_b = (const float*)d_in[2];
    const float* ln2_g = (const float*)d_in[3];
    const float* ln2_b = (const float*)d_in[4];
    const float* Wq    = (const float*)d_in[5];
    const float* Wk    = (const float*)d_in[6];
    const float* Wv    = (const float*)d_in[7];
    const float* Wp    = (const float*)d_in[8];
    const float* bp    = (const float*)d_in[9];
    const float* W1    = (const float*)d_in[10];
    const float* b1    = (const float*)d_in[11];
    const float* W2    = (const float*)d_in[12];
    const float* b2    = (const float*)d_in[13];
    float* out = (float*)d_out;

    __nv_bfloat16 *ln1, *wqk;
    __half *h1h, *vhp, *attnh, *h2h, *hidh, *wvh, *wph, *w1h, *w2h;
    float *qkp, *x2;
    cudaGetSymbolAddress((void**)&ln1,   g_ln1);
    cudaGetSymbolAddress((void**)&h1h,   g_h1h);
    cudaGetSymbolAddress((void**)&qkp,   g_qk);
    cudaGetSymbolAddress((void**)&vhp,   g_vh);
    cudaGetSymbolAddress((void**)&attnh, g_attnh);
    cudaGetSymbolAddress((void**)&x2,    g_x2);
    cudaGetSymbolAddress((void**)&h2h,   g_h2h);
    cudaGetSymbolAddress((void**)&hidh,  g_hidh);
    cudaGetSymbolAddress((void**)&wqk,   g_wqk);
    cudaGetSymbolAddress((void**)&wvh,   g_wvh);
    cudaGetSymbolAddress((void**)&wph,   g_wph);
    cudaGetSymbolAddress((void**)&w1h,   g_w1h);
    cudaGetSymbolAddress((void**)&w2h,   g_w2h);

    cudaFuncSetAttribute(gemm_qkv,       cudaFuncAttributeMaxDynamicSharedMemorySize, GSMEMQ);
    cudaFuncSetAttribute((gemm16<3,6>),  cudaFuncAttributeMaxDynamicSharedMemorySize, GSMEM2);
    cudaFuncSetAttribute((gemm16<2,6>),  cudaFuncAttributeMaxDynamicSharedMemorySize, GSMEM2);
    cudaFuncSetAttribute((gemm16<1,24>), cudaFuncAttributeMaxDynamicSharedMemorySize, GSMEM2);

    // 1) LN1 (bf16 split + fp16) + all weight prep + sem zero
    stage1_kernel<<<LN_BLOCKS + PREP_BLOCKS, 128>>>(x, ln1_g, ln1_b, ln1, h1h,
                                                    Wq, Wk, Wv, Wp, W1, W2);
    // 2) fat QKV: QK (3-pass bf16 -> fp32) + V (1-pass fp16 -> fp16)
    gemm_qkv<<<dim3(9, N_TOK / 256), 512, GSMEMQ>>>(ln1, wqk, h1h, wvh, qkp, vhp);
    // 3) attention -> fp16
    attn_kernel<<<dim3(2048, NHEAD), 128>>>(qkp, vhp, attnh);
    // 4) proj + bias + residual(x) -> fp32 x2, with fused LN2 -> h2h
    gemm16<3,6><<<dim3(3, N_TOK / 128), 256, GSMEM2>>>(attnh, wph, bp, x, x2, EMB,
                                                       ln2_g, ln2_b, h2h);
    // 5) MLP up + relu -> fp16 hidden
    gemm16<2,6><<<dim3(12, N_TOK / 128), 256, GSMEM2>>>(h2h, w1h, b1, nullptr, hidh, FF,
                                                        nullptr, nullptr, nullptr);
    // 6) MLP down (K=1536) + bias + residual(x2) -> out
    gemm16<1,24><<<dim3(3, N_TOK / 128), 256, GSMEM2>>>(hidh, w2h, b2, x2, out, EMB,
                                                        nullptr, nullptr, nullptr);
}